// round 11
// baseline (speedup 1.0000x reference)
#include <cuda_runtime.h>

// Spherical harmonics embedding, L=4 -> 50 channels (re,im interleaved, m=-l..l).
// out[pt*50 + ch]. Per-WARP smem staging (stride-52 rows, 16B aligned, STS.128),
// __syncwarp only (no block barrier) so warps free-run and stores pipeline,
// drain with strength-reduced addressing + __stcs streaming stores.

#define TILE 128
#define NCH  50
#define SROW 52   // 16B-aligned rows; smem idx of linear e = e + 2*(e/50)

__global__ __launch_bounds__(TILE)
void sh_embed_kernel(const float* __restrict__ dirs,
                     float* __restrict__ out,
                     int npts)
{
    __shared__ float sm[TILE * SROW];

    const int tid  = threadIdx.x;
    const int warp = tid >> 5;
    const int lane = tid & 31;
    const int pt   = blockIdx.x * TILE + tid;

    float* wbase = sm + warp * (32 * SROW);   // this warp's private slice
    float* row   = wbase + lane * SROW;

    float x = 0.0f, y = 0.0f, z = 1.0f;
    if (pt < npts) {
        x = dirs[pt * 3 + 0];
        y = dirs[pt * 3 + 1];
        z = dirs[pt * 3 + 2];
    }

    const float ct = fminf(fmaxf(z, -1.0f), 1.0f);
    const float st = sqrtf(fmaxf(1.0f - ct * ct, 0.0f));

    // cos(phi), sin(phi) from x,y directly (== atan2 path)
    const float r2 = x * x + y * y;
    float cp, sp;
    if (r2 > 0.0f) {
        const float rinv = rsqrtf(r2);
        cp = x * rinv;
        sp = y * rinv;
    } else {
        cp = 1.0f; sp = 0.0f;
    }

    // cos(m*phi), sin(m*phi) via angle-addition recurrence
    const float c1 = cp,              s1 = sp;
    const float c2 = cp*c1 - sp*s1,   s2 = sp*c1 + cp*s1;
    const float c3 = cp*c2 - sp*s2,   s3 = sp*c2 + cp*s2;
    const float c4 = cp*c3 - sp*s3,   s4 = sp*c3 + cp*s3;

    // Associated Legendre (Condon-Shortley), unrolled for L=4
    const float P00 = 1.0f;
    const float P11 = -st;
    const float P22 = -3.0f * st * P11;          //  3 st^2
    const float P33 = -5.0f * st * P22;          // -15 st^3
    const float P44 = -7.0f * st * P33;          // 105 st^4
    const float P10 = ct;
    const float P21 = 3.0f * ct * P11;
    const float P32 = 5.0f * ct * P22;
    const float P43 = 7.0f * ct * P33;
    const float P20 = 0.5f * (3.0f * ct * P10 - P00);
    const float P30 = (5.0f * ct * P20 - 2.0f * P10) * (1.0f/3.0f);
    const float P40 = (7.0f * ct * P30 - 3.0f * P20) * 0.25f;
    const float P31 = 0.5f * (5.0f * ct * P21 - 3.0f * P11);
    const float P41 = (7.0f * ct * P31 - 4.0f * P21) * (1.0f/3.0f);
    const float P42 = 0.5f * (7.0f * ct * P32 - 5.0f * P22);

    // Normalization N(l,m) = sqrt((2l+1)/(4pi) * (l-m)!/(l+m)!)
    const float b00 = 0.28209479177387814f * P00;
    const float b10 = 0.48860251190291992f * P10;
    const float b11 = 0.34549414947133547f * P11;
    const float b20 = 0.63078313050504009f * P20;
    const float b21 = 0.25751613468212653f * P21;
    const float b22 = 0.12875806734106327f * P22;
    const float b30 = 0.74635266518023078f * P30;
    const float b31 = 0.21545345607610053f * P31;
    const float b32 = 0.06813236509555269f * P32;
    const float b33 = 0.02781492157551894f * P33;
    const float b40 = 0.84628437532163443f * P40;
    const float b41 = 0.18923493915151202f * P41;
    const float b42 = 0.04460310290381929f * P42;
    const float b43 = 0.01192068067522273f * P43;
    const float b44 = 0.00421459707090460f * P44;

    // Vectorized smem writes (rows are 16B aligned with SROW=52).
    float4* row4 = reinterpret_cast<float4*>(row);
    row4[0]  = make_float4( b00,       0.0f,     -b11*c1,   b11*s1);
    row4[1]  = make_float4( b10,       0.0f,      b11*c1,   b11*s1);
    row4[2]  = make_float4( b22*c2,   -b22*s2,   -b21*c1,   b21*s1);
    row4[3]  = make_float4( b20,       0.0f,      b21*c1,   b21*s1);
    row4[4]  = make_float4( b22*c2,    b22*s2,   -b33*c3,   b33*s3);
    row4[5]  = make_float4( b32*c2,   -b32*s2,   -b31*c1,   b31*s1);
    row4[6]  = make_float4( b30,       0.0f,      b31*c1,   b31*s1);
    row4[7]  = make_float4( b32*c2,    b32*s2,    b33*c3,   b33*s3);
    row4[8]  = make_float4( b44*c4,   -b44*s4,   -b43*c3,   b43*s3);
    row4[9]  = make_float4( b42*c2,   -b42*s2,   -b41*c1,   b41*s1);
    row4[10] = make_float4( b40,       0.0f,      b41*c1,   b41*s1);
    row4[11] = make_float4( b42*c2,    b42*s2,    b43*c3,   b43*s3);
    reinterpret_cast<float2*>(row)[24] = make_float2(b44*c4, b44*s4);

    __syncwarp();   // warp-local staging complete; no block barrier

    // ---- Per-warp drain: 32 pts * 50 ch = 1600 floats = 400 float4 ----
    // smem index of local linear float j = j + 2*(j/50).
    const int warpPt0 = blockIdx.x * TILE + warp * 32;   // first point of warp
    float4* out4 = reinterpret_cast<float4*>(out)
                 + (size_t)warpPt0 * (NCH / 2) / 2;      // warpPt0*50/4 (warpPt0*50 % 4 == 0)

    if (warpPt0 + 32 <= npts) {
        // Full warp tile: 12 full rounds + half round.
        #pragma unroll
        for (int it = 0; it < 12; it++) {
            const int i  = lane + it * 32;    // float4 index < 384
            const int j  = i * 4;
            const int r  = j / 50;
            const int rb = (j + 2) / 50;      // handles the lone j%50==48 crossing
            float4 v;
            v.x = wbase[j + 0 + 2 * r];
            v.y = wbase[j + 1 + 2 * r];
            v.z = wbase[j + 2 + 2 * rb];
            v.w = wbase[j + 3 + 2 * rb];
            __stcs(&out4[i], v);
        }
        if (lane < 16) {                      // float4 index 384..399
            const int i  = lane + 384;
            const int j  = i * 4;
            const int r  = j / 50;
            const int rb = (j + 2) / 50;
            float4 v;
            v.x = wbase[j + 0 + 2 * r];
            v.y = wbase[j + 1 + 2 * r];
            v.z = wbase[j + 2 + 2 * rb];
            v.w = wbase[j + 3 + 2 * rb];
            __stcs(&out4[i], v);
        }
    } else if (warpPt0 < npts) {
        // Guarded scalar tail (partial warp); no cross-warp dependence.
        const long long total = (long long)npts * NCH;
        const long long baseF = (long long)warpPt0 * NCH;
        for (int j = lane; j < 32 * NCH; j += 32) {
            const long long g = baseF + j;
            if (g < total) out[g] = wbase[j + 2 * (j / 50)];
        }
    }
}

extern "C" void kernel_launch(void* const* d_in, const int* in_sizes, int n_in,
                              void* d_out, int out_size)
{
    const float* dirs = (const float*)d_in[0];
    float* out = (float*)d_out;
    const int npts = in_sizes[0] / 3;

    const int grid = (npts + TILE - 1) / TILE;
    sh_embed_kernel<<<grid, TILE>>>(dirs, out, npts);
}

// round 12
// speedup vs baseline: 1.0111x; 1.0111x over previous
#include <cuda_runtime.h>

// Spherical harmonics embedding, L=4 -> 50 channels (re,im interleaved, m=-l..l).
// out[pt*50 + ch]. Per-warp smem staging in OUTPUT-LINEAR layout (stride-50,
// unpadded): writers use STS.64 (2-way conflicts, overlapped with compute),
// drain is pure contiguous LDS.128 + STG.128 streaming stores — no gathers,
// no divides, conflict-free.

#define TILE 128
#define NCH  50

__global__ __launch_bounds__(TILE)
void sh_embed_kernel(const float* __restrict__ dirs,
                     float* __restrict__ out,
                     int npts)
{
    __shared__ __align__(16) float sm[TILE * NCH];   // 25.6 KB

    const int tid  = threadIdx.x;
    const int warp = tid >> 5;
    const int lane = tid & 31;
    const int pt   = blockIdx.x * TILE + tid;

    float* wbase = sm + warp * (32 * NCH);    // this warp's 1600-float slice
    float* row   = wbase + lane * NCH;        // 200B stride -> 8B aligned

    float x = 0.0f, y = 0.0f, z = 1.0f;
    if (pt < npts) {
        x = dirs[pt * 3 + 0];
        y = dirs[pt * 3 + 1];
        z = dirs[pt * 3 + 2];
    }

    const float ct = fminf(fmaxf(z, -1.0f), 1.0f);
    const float st = sqrtf(fmaxf(1.0f - ct * ct, 0.0f));

    // cos(phi), sin(phi) from x,y directly (== atan2 path)
    const float r2 = x * x + y * y;
    float cp, sp;
    if (r2 > 0.0f) {
        const float rinv = rsqrtf(r2);
        cp = x * rinv;
        sp = y * rinv;
    } else {
        cp = 1.0f; sp = 0.0f;
    }

    // cos(m*phi), sin(m*phi) via angle-addition recurrence
    const float c1 = cp,              s1 = sp;
    const float c2 = cp*c1 - sp*s1,   s2 = sp*c1 + cp*s1;
    const float c3 = cp*c2 - sp*s2,   s3 = sp*c2 + cp*s2;
    const float c4 = cp*c3 - sp*s3,   s4 = sp*c3 + cp*s3;

    // Associated Legendre (Condon-Shortley), unrolled for L=4
    const float P00 = 1.0f;
    const float P11 = -st;
    const float P22 = -3.0f * st * P11;          //  3 st^2
    const float P33 = -5.0f * st * P22;          // -15 st^3
    const float P44 = -7.0f * st * P33;          // 105 st^4
    const float P10 = ct;
    const float P21 = 3.0f * ct * P11;
    const float P32 = 5.0f * ct * P22;
    const float P43 = 7.0f * ct * P33;
    const float P20 = 0.5f * (3.0f * ct * P10 - P00);
    const float P30 = (5.0f * ct * P20 - 2.0f * P10) * (1.0f/3.0f);
    const float P40 = (7.0f * ct * P30 - 3.0f * P20) * 0.25f;
    const float P31 = 0.5f * (5.0f * ct * P21 - 3.0f * P11);
    const float P41 = (7.0f * ct * P31 - 4.0f * P21) * (1.0f/3.0f);
    const float P42 = 0.5f * (7.0f * ct * P32 - 5.0f * P22);

    // Normalization N(l,m) = sqrt((2l+1)/(4pi) * (l-m)!/(l+m)!)
    const float b00 = 0.28209479177387814f * P00;
    const float b10 = 0.48860251190291992f * P10;
    const float b11 = 0.34549414947133547f * P11;
    const float b20 = 0.63078313050504009f * P20;
    const float b21 = 0.25751613468212653f * P21;
    const float b22 = 0.12875806734106327f * P22;
    const float b30 = 0.74635266518023078f * P30;
    const float b31 = 0.21545345607610053f * P31;
    const float b32 = 0.06813236509555269f * P32;
    const float b33 = 0.02781492157551894f * P33;
    const float b40 = 0.84628437532163443f * P40;
    const float b41 = 0.18923493915151202f * P41;
    const float b42 = 0.04460310290381929f * P42;
    const float b43 = 0.01192068067522273f * P43;
    const float b44 = 0.00421459707090460f * P44;

    // Stage in output-linear order: 25 x STS.64 (rows 8B-aligned).
    float2* row2 = reinterpret_cast<float2*>(row);
    row2[0]  = make_float2( b00,     0.0f   );
    row2[1]  = make_float2(-b11*c1,  b11*s1 );
    row2[2]  = make_float2( b10,     0.0f   );
    row2[3]  = make_float2( b11*c1,  b11*s1 );
    row2[4]  = make_float2( b22*c2, -b22*s2 );
    row2[5]  = make_float2(-b21*c1,  b21*s1 );
    row2[6]  = make_float2( b20,     0.0f   );
    row2[7]  = make_float2( b21*c1,  b21*s1 );
    row2[8]  = make_float2( b22*c2,  b22*s2 );
    row2[9]  = make_float2(-b33*c3,  b33*s3 );
    row2[10] = make_float2( b32*c2, -b32*s2 );
    row2[11] = make_float2(-b31*c1,  b31*s1 );
    row2[12] = make_float2( b30,     0.0f   );
    row2[13] = make_float2( b31*c1,  b31*s1 );
    row2[14] = make_float2( b32*c2,  b32*s2 );
    row2[15] = make_float2( b33*c3,  b33*s3 );
    row2[16] = make_float2( b44*c4, -b44*s4 );
    row2[17] = make_float2(-b43*c3,  b43*s3 );
    row2[18] = make_float2( b42*c2, -b42*s2 );
    row2[19] = make_float2(-b41*c1,  b41*s1 );
    row2[20] = make_float2( b40,     0.0f   );
    row2[21] = make_float2( b41*c1,  b41*s1 );
    row2[22] = make_float2( b42*c2,  b42*s2 );
    row2[23] = make_float2( b43*c3,  b43*s3 );
    row2[24] = make_float2( b44*c4,  b44*s4 );

    __syncwarp();   // warp-private slice; no block barrier needed

    // ---- Per-warp drain: 400 contiguous float4 (LDS.128 + STG.128) ----
    const int warpPt0 = blockIdx.x * TILE + warp * 32;
    const float4* wbase4 = reinterpret_cast<const float4*>(wbase);
    float4* out4 = reinterpret_cast<float4*>(out) + (size_t)warpPt0 * NCH / 4;

    if (warpPt0 + 32 <= npts) {
        #pragma unroll
        for (int it = 0; it < 12; it++) {
            const int i = lane + it * 32;     // < 384
            __stcs(&out4[i], wbase4[i]);
        }
        if (lane < 16) {                      // 384..399
            const int i = lane + 384;
            __stcs(&out4[i], wbase4[i]);
        }
    } else if (warpPt0 < npts) {
        // Guarded scalar tail (partial warp).
        const long long total = (long long)npts * NCH;
        const long long baseF = (long long)warpPt0 * NCH;
        for (int j = lane; j < 32 * NCH; j += 32) {
            const long long g = baseF + j;
            if (g < total) out[g] = wbase[j];
        }
    }
}

extern "C" void kernel_launch(void* const* d_in, const int* in_sizes, int n_in,
                              void* d_out, int out_size)
{
    const float* dirs = (const float*)d_in[0];
    float* out = (float*)d_out;
    const int npts = in_sizes[0] / 3;

    const int grid = (npts + TILE - 1) / TILE;
    sh_embed_kernel<<<grid, TILE>>>(dirs, out, npts);
}